// round 5
// baseline (speedup 1.0000x reference)
#include <cuda_runtime.h>
#include <math.h>

#define NROWS 32768
#define KDIM  1024

// ---------------- device scratch (no allocations allowed) ----------------
__device__ alignas(16) float g_gates[4096];
__device__ alignas(16) float g_h[2048];
__device__ alignas(16) float g_c[2048];
__device__ alignas(16) float g_zconst[1024];
__device__ alignas(16) float g_context[1024];
__device__ alignas(16) float g_wenc[1024];
__device__ alignas(16) float g_logits[NROWS];
__device__ alignas(16) float g_attn[NROWS];
__device__ alignas(16) float g_colpart[64 * 1024];

// ---------------- f32x2 packed-FMA helpers (Blackwell FFMA2) ----------------
__device__ __forceinline__ unsigned long long f32x2_dup(float b) {
    unsigned long long r;
    unsigned u = __float_as_uint(b);
    asm("mov.b64 %0, {%1, %2};" : "=l"(r) : "r"(u), "r"(u));
    return r;
}
__device__ __forceinline__ void f32x2_fma(unsigned long long& d,
                                          unsigned long long a,
                                          unsigned long long b) {
    asm("fma.rn.f32x2 %0, %1, %2, %3;" : "=l"(d) : "l"(a), "l"(b), "l"(d));
}
__device__ __forceinline__ float2 f32x2_unpack(unsigned long long v) {
    unsigned lo, hi;
    asm("mov.b64 {%0, %1}, %2;" : "=r"(lo), "=r"(hi) : "l"(v));
    return make_float2(__uint_as_float(lo), __uint_as_float(hi));
}

__device__ __forceinline__ float sigmoidf_(float x) { return 1.f / (1.f + expf(-x)); }

// ---------------- LSTM ----------------
// gates[r] = dot(W_ih[r], x) + dot(W_hh[r], h_prev) + b_ih[r] + b_hh[r], r in [0,4096)
__global__ void lstm_gates_kernel(const float* __restrict__ Wih,
                                  const float* __restrict__ Whh,
                                  const float* __restrict__ bih,
                                  const float* __restrict__ bhh,
                                  const float* x_in,
                                  const float* __restrict__ hprev) {
    int gw = (blockIdx.x * 256 + threadIdx.x) >> 5;  // 0..4095
    int lane = threadIdx.x & 31;
    const float* x = x_in ? x_in : g_h;  // layer 1 input = layer 0 h
    const float4* wi = (const float4*)(Wih + (size_t)gw * KDIM);
    const float4* wh = (const float4*)(Whh + (size_t)gw * KDIM);
    const float4* x4 = (const float4*)x;
    const float4* h4 = (const float4*)hprev;
    float s = 0.f;
#pragma unroll
    for (int i = 0; i < 8; ++i) {
        float4 a = wi[lane + i * 32], b = x4[lane + i * 32];
        s = fmaf(a.x, b.x, fmaf(a.y, b.y, fmaf(a.z, b.z, fmaf(a.w, b.w, s))));
        float4 c2 = wh[lane + i * 32], d2 = h4[lane + i * 32];
        s = fmaf(c2.x, d2.x, fmaf(c2.y, d2.y, fmaf(c2.z, d2.z, fmaf(c2.w, d2.w, s))));
    }
#pragma unroll
    for (int o = 16; o; o >>= 1) s += __shfl_xor_sync(0xffffffffu, s, o);
    if (lane == 0) g_gates[gw] = s + bih[gw] + bhh[gw];
}

__global__ void lstm_combine_kernel(const float* __restrict__ c_prev, int layer) {
    int j = threadIdx.x;  // 1024 threads
    float gi = g_gates[j];
    float gf = g_gates[1024 + j];
    float gg = g_gates[2048 + j];
    float go = g_gates[3072 + j];
    float c = sigmoidf_(gf) * c_prev[j] + sigmoidf_(gi) * tanhf(gg);
    float h = sigmoidf_(go) * tanhf(c);
    g_c[layer * 1024 + j] = c;
    g_h[layer * 1024 + j] = h;
}

// ---------------- generic 1024x1024 matvec ----------------
// x_sel: 1 -> g_h+1024 (lstm output), 2 -> g_wenc, 3 -> g_context
// out_sel: 0 -> g_zconst, 1 -> g_context
__global__ void matvec_kernel(const float* __restrict__ W,
                              const float* __restrict__ b0,
                              const float* __restrict__ b1,
                              const float* __restrict__ b2,
                              int x_sel, int out_sel) {
    int gw = (blockIdx.x * 256 + threadIdx.x) >> 5;  // 0..1023
    int lane = threadIdx.x & 31;
    const float* x = (x_sel == 1) ? (g_h + 1024) : (x_sel == 2 ? g_wenc : g_context);
    const float4* wr = (const float4*)(W + (size_t)gw * KDIM);
    const float4* x4 = (const float4*)x;
    float s = 0.f;
#pragma unroll
    for (int i = 0; i < 8; ++i) {
        float4 a = wr[lane + i * 32], b = x4[lane + i * 32];
        s = fmaf(a.x, b.x, fmaf(a.y, b.y, fmaf(a.z, b.z, fmaf(a.w, b.w, s))));
    }
#pragma unroll
    for (int o = 16; o; o >>= 1) s += __shfl_xor_sync(0xffffffffu, s, o);
    if (lane == 0) {
        if (b0) s += b0[gw];
        if (b1) s += b1[gw];
        if (b2) s += b2[gw];
        if (out_sel == 0) g_zconst[gw] = s;
        else              g_context[gw] = s;
    }
}

// ---------------- fused score GEMM ----------------
// logits[n] = sum_j v[j] * tanh( (A @ W^T)[n,j] + zconst[j] + cov[n]*wc[j] )
// A: [N,1024] row-major, W: [1024,1024] row-major (K contiguous for both).
#define BM 128
#define BN 128
#define BK 16
#define NKT (KDIM / BK)  // 64
#define NJT (KDIM / BN)  // 8

__global__ __launch_bounds__(256, 1)
void score_gemm_kernel(const float* __restrict__ A, const float* __restrict__ W,
                       const float* __restrict__ cov, const float* __restrict__ wc,
                       const float* __restrict__ vvec) {
    __shared__ alignas(16) float As[BK][BM];
    __shared__ alignas(16) float Bs[BK][BN];
    __shared__ float red[BM][17];
    __shared__ float rowsum[BM];
    __shared__ float s_cov[BM];
    __shared__ float s_cv[BN], s_wc[BN], s_v[BN];

    const int tid = threadIdx.x;
    const int n0 = blockIdx.x * BM;
    const int tx = tid & 15;   // col group (8 cols)
    const int ty = tid >> 4;   // row group (8 rows)
    const float4* A4 = (const float4*)A;
    const float4* W4 = (const float4*)W;

    if (tid < BM) {
        rowsum[tid] = 0.f;
        s_cov[tid] = cov[n0 + tid];
    }

    for (int jt = 0; jt < NJT; ++jt) {
        __syncthreads();
        if (tid < BN) {
            int j = jt * BN + tid;
            s_cv[tid] = g_zconst[j];
            s_wc[tid] = wc[j];
            s_v[tid]  = vvec[j];
        }
        unsigned long long acc[4][8];
#pragma unroll
        for (int ii = 0; ii < 4; ++ii)
#pragma unroll
            for (int j = 0; j < 8; ++j) acc[ii][j] = 0ull;

        for (int kt = 0; kt < NKT; ++kt) {
            __syncthreads();
#pragma unroll
            for (int r = 0; r < 2; ++r) {
                int q = tid * 2 + r;            // 0..511
                int row = q >> 2, kq = q & 3;
                float4 va = A4[(size_t)(n0 + row) * (KDIM / 4) + kt * 4 + kq];
                As[kq * 4 + 0][row] = va.x; As[kq * 4 + 1][row] = va.y;
                As[kq * 4 + 2][row] = va.z; As[kq * 4 + 3][row] = va.w;
                float4 vb = W4[(size_t)(jt * BN + row) * (KDIM / 4) + kt * 4 + kq];
                Bs[kq * 4 + 0][row] = vb.x; Bs[kq * 4 + 1][row] = vb.y;
                Bs[kq * 4 + 2][row] = vb.z; Bs[kq * 4 + 3][row] = vb.w;
            }
            __syncthreads();
#pragma unroll
            for (int kk = 0; kk < BK; ++kk) {
                const ulonglong2* pa = (const ulonglong2*)&As[kk][ty * 8];
                ulonglong2 a01 = pa[0], a23 = pa[1];
                unsigned long long a2[4] = {a01.x, a01.y, a23.x, a23.y};
                const float4* pb = (const float4*)&Bs[kk][tx * 8];
                float4 b0 = pb[0], b1 = pb[1];
                unsigned long long bb[8];
                bb[0] = f32x2_dup(b0.x); bb[1] = f32x2_dup(b0.y);
                bb[2] = f32x2_dup(b0.z); bb[3] = f32x2_dup(b0.w);
                bb[4] = f32x2_dup(b1.x); bb[5] = f32x2_dup(b1.y);
                bb[6] = f32x2_dup(b1.z); bb[7] = f32x2_dup(b1.w);
#pragma unroll
                for (int ii = 0; ii < 4; ++ii)
#pragma unroll
                    for (int j = 0; j < 8; ++j)
                        f32x2_fma(acc[ii][j], a2[ii], bb[j]);
            }
        }
        // epilogue: reduce tanh over this 128-col tile into per-row partials
        float rp[8];
#pragma unroll
        for (int i = 0; i < 8; ++i) rp[i] = 0.f;
#pragma unroll
        for (int ii = 0; ii < 4; ++ii) {
            float c0 = s_cov[ty * 8 + 2 * ii];
            float c1 = s_cov[ty * 8 + 2 * ii + 1];
#pragma unroll
            for (int j = 0; j < 8; ++j) {
                float2 ch = f32x2_unpack(acc[ii][j]);
                int jc = tx * 8 + j;
                float base = s_cv[jc];
                float w    = s_wc[jc];
                float vv   = s_v[jc];
                rp[2 * ii]     += vv * tanhf(ch.x + base + c0 * w);
                rp[2 * ii + 1] += vv * tanhf(ch.y + base + c1 * w);
            }
        }
#pragma unroll
        for (int i = 0; i < 8; ++i) red[ty * 8 + i][tx] = rp[i];
        __syncthreads();
        if (tid < BM) {
            float s = 0.f;
#pragma unroll
            for (int t = 0; t < 16; ++t) s += red[tid][t];
            rowsum[tid] += s;
        }
    }
    __syncthreads();
    if (tid < BM) g_logits[n0 + tid] = rowsum[tid];
}

// ---------------- softmax (single CTA, deterministic) ----------------
// logit = g_logits[n] + vb; optional relu; prob = softmax; cov_out = cov + prob
__global__ void softmax_kernel(const float* __restrict__ vbp,
                               const float* __restrict__ cov,
                               float* __restrict__ prob_ext,
                               float* __restrict__ cov_out,
                               int do_relu) {
    __shared__ float shred[32];
    __shared__ float bval;
    int tid = threadIdx.x;  // 1024
    float vb = vbp[0];
    float lmax = -3.4e38f;
    for (int n = tid; n < NROWS; n += 1024) {
        float l = g_logits[n] + vb;
        if (do_relu) l = fmaxf(l, 0.f);
        g_logits[n] = l;
        lmax = fmaxf(lmax, l);
    }
#pragma unroll
    for (int o = 16; o; o >>= 1) lmax = fmaxf(lmax, __shfl_xor_sync(0xffffffffu, lmax, o));
    if ((tid & 31) == 0) shred[tid >> 5] = lmax;
    __syncthreads();
    if (tid < 32) {
        float v = shred[tid];
#pragma unroll
        for (int o = 16; o; o >>= 1) v = fmaxf(v, __shfl_xor_sync(0xffffffffu, v, o));
        if (tid == 0) bval = v;
    }
    __syncthreads();
    float m = bval;
    float lsum = 0.f;
    for (int n = tid; n < NROWS; n += 1024) lsum += expf(g_logits[n] - m);
#pragma unroll
    for (int o = 16; o; o >>= 1) lsum += __shfl_xor_sync(0xffffffffu, lsum, o);
    __syncthreads();
    if ((tid & 31) == 0) shred[tid >> 5] = lsum;
    __syncthreads();
    if (tid < 32) {
        float v = shred[tid];
#pragma unroll
        for (int o = 16; o; o >>= 1) v += __shfl_xor_sync(0xffffffffu, v, o);
        if (tid == 0) bval = v;
    }
    __syncthreads();
    float inv = 1.f / bval;
    float* prob = prob_ext ? prob_ext : g_attn;
    for (int n = tid; n < NROWS; n += 1024) {
        float p = expf(g_logits[n] - m) * inv;
        prob[n] = p;
        if (cov_out) cov_out[n] = cov[n] + p;
    }
}

// ---------------- weighted column sum: g_wenc = enc^T @ attn ----------------
__global__ void wsum_partial_kernel(const float* __restrict__ enc) {
    int col = blockIdx.x * 256 + threadIdx.x;  // gridDim.x = 4
    int n0 = blockIdx.y * 512;                 // gridDim.y = 64
    float s = 0.f;
#pragma unroll 4
    for (int n = n0; n < n0 + 512; ++n)
        s = fmaf(g_attn[n], enc[(size_t)n * KDIM + col], s);
    g_colpart[blockIdx.y * KDIM + col] = s;
}
__global__ void wsum_reduce_kernel() {
    int col = threadIdx.x;  // 1024
    float s = 0.f;
#pragma unroll
    for (int i = 0; i < 64; ++i) s += g_colpart[i * KDIM + col];
    g_wenc[col] = s;
}

// ---------------- h/c output copy ----------------
__global__ void copy_hc_kernel(float* __restrict__ oh, float* __restrict__ oc) {
    int i = blockIdx.x * blockDim.x + threadIdx.x;
    if (i < 2048) {
        oh[i] = g_h[i];
        oc[i] = g_c[i];
    }
}

// ---------------- launch ----------------
extern "C" void kernel_launch(void* const* d_in, const int* in_sizes, int n_in,
                              void* d_out, int out_size) {
    (void)in_sizes; (void)n_in;
    const float* inp   = (const float*)d_in[0];
    const float* h0    = (const float*)d_in[1];
    const float* c0    = (const float*)d_in[2];
    const float* enc   = (const float*)d_in[3];
    const float* cov_g = (const float*)d_in[4];
    const float* cov_p = (const float*)d_in[5];
    const float* Wih   = (const float*)d_in[6];
    const float* Whh   = (const float*)d_in[7];
    const float* bih   = (const float*)d_in[8];
    const float* bhh   = (const float*)d_in[9];
    const float* gw1   = (const float*)d_in[10];
    const float* gb1   = (const float*)d_in[11];
    const float* gw2   = (const float*)d_in[12];
    const float* gb2   = (const float*)d_in[13];
    const float* gwc   = (const float*)d_in[14];
    const float* gbc   = (const float*)d_in[15];
    const float* gv    = (const float*)d_in[16];
    const float* gvb   = (const float*)d_in[17];
    const float* pw1   = (const float*)d_in[18];
    const float* pb1   = (const float*)d_in[19];
    const float* pw2   = (const float*)d_in[20];
    const float* pb2   = (const float*)d_in[21];
    const float* pwc   = (const float*)d_in[22];
    const float* pbc   = (const float*)d_in[23];
    const float* pv    = (const float*)d_in[24];
    const float* pvb   = (const float*)d_in[25];

    float* out = (float*)d_out;
    const int FULL = 32768 + 2048 + 2048 + 32768 + 32768;  // 102400
    bool full = out_size >= FULL;
    float* out_h  = full ? out + 32768 : nullptr;
    float* out_c  = full ? out + 34816 : nullptr;
    float* out_cg = full ? out + 36864 : nullptr;
    float* out_cp = full ? out + 69632 : nullptr;

    // LSTM layer 0 (x = _input, h/c = h0[0]/c0[0])
    lstm_gates_kernel<<<512, 256>>>(Wih, Whh, bih, bhh, inp, h0);
    lstm_combine_kernel<<<1, 1024>>>(c0, 0);
    // LSTM layer 1 (x = g_h[0:1024], h/c = h0[1]/c0[1])
    lstm_gates_kernel<<<512, 256>>>(Wih + (size_t)4096 * 1024, Whh + (size_t)4096 * 1024,
                                    bih + 4096, bhh + 4096, nullptr, h0 + 1024);
    lstm_combine_kernel<<<1, 1024>>>(c0 + 1024, 1);

    // zconst_g = g_w2 @ lstm_out + g_b2 + g_b1 + g_bc
    matvec_kernel<<<128, 256>>>(gw2, gb2, gb1, gbc, /*x_sel=*/1, /*out_sel=*/0);

    // glimpse attention logits (fused GEMM + tanh + v-dot)
    score_gemm_kernel<<<256, 256>>>(enc, gw1, cov_g, gwc, gv);
    // attn = softmax(logits + vb); cov_g_new = cov_g + attn
    softmax_kernel<<<1, 1024>>>(gvb, cov_g, nullptr, out_cg, 0);

    // weighted_enc = enc^T @ attn  (context = g_w1 @ weighted_enc + g_b1)
    wsum_partial_kernel<<<dim3(4, 64), 256>>>(enc);
    wsum_reduce_kernel<<<1, 1024>>>();
    matvec_kernel<<<128, 256>>>(gw1, gb1, nullptr, nullptr, /*x_sel=*/2, /*out_sel=*/1);

    // zconst_p = p_w2 @ context + p_b2 + p_b1 + p_bc
    matvec_kernel<<<128, 256>>>(pw2, pb2, pb1, pbc, /*x_sel=*/3, /*out_sel=*/0);

    // pointer logits
    score_gemm_kernel<<<256, 256>>>(enc, pw1, cov_p, pwc, pv);
    // u = relu(logits + vb); cond_p = softmax(u) -> d_out; cov_p_new = cov_p + cond_p
    softmax_kernel<<<1, 1024>>>(pvb, cov_p, out, out_cp, 1);

    if (full) copy_hc_kernel<<<2, 1024>>>(out_h, out_c);
}

// round 11
// speedup vs baseline: 2.4885x; 2.4885x over previous
#include <cuda_runtime.h>
#include <cuda_bf16.h>
#include <math.h>
#include <cstdint>

#define NROWS 32768
#define KDIM  1024

// ---------------- device scratch (no allocations allowed) ----------------
__device__ alignas(16) float g_gates[4096];
__device__ alignas(16) float g_h[2048];
__device__ alignas(16) float g_c[2048];
__device__ alignas(16) float g_zconst[1024];
__device__ alignas(16) float g_context[1024];
__device__ alignas(16) float g_wenc[1024];
__device__ alignas(16) float g_logits[NROWS];
__device__ alignas(16) float g_attn[NROWS];
__device__ alignas(16) float g_colpart[64 * 1024];

// bf16 hi/lo split scratch for tensor-core GEMM
__device__ alignas(16) __nv_bfloat16 g_Ahi[(size_t)NROWS * KDIM];
__device__ alignas(16) __nv_bfloat16 g_Alo[(size_t)NROWS * KDIM];
__device__ alignas(16) __nv_bfloat16 g_Whi[2][(size_t)KDIM * KDIM];
__device__ alignas(16) __nv_bfloat16 g_Wlo[2][(size_t)KDIM * KDIM];

// ---------------- PTX helpers (baseline sm_80/sm_90 instructions ONLY) ----------------
__device__ __forceinline__ uint32_t smem_u32(const void* p) {
    uint32_t a;
    asm("{ .reg .u64 t; cvta.to.shared.u64 t, %1; cvt.u32.u64 %0, t; }" : "=r"(a) : "l"(p));
    return a;
}
__device__ __forceinline__ void cpa16(uint32_t s, const void* g) {
    asm volatile("cp.async.cg.shared.global [%0], [%1], 16;" :: "r"(s), "l"(g));
}
__device__ __forceinline__ void cp_commit() { asm volatile("cp.async.commit_group;" ::: "memory"); }
__device__ __forceinline__ void cp_wait1()  { asm volatile("cp.async.wait_group 1;" ::: "memory"); }
__device__ __forceinline__ void cp_wait0()  { asm volatile("cp.async.wait_group 0;" ::: "memory"); }

__device__ __forceinline__ void ldsm_x4(uint32_t* r, uint32_t addr) {
    asm volatile("ldmatrix.sync.aligned.m8n8.x4.shared.b16 {%0,%1,%2,%3}, [%4];"
                 : "=r"(r[0]), "=r"(r[1]), "=r"(r[2]), "=r"(r[3]) : "r"(addr));
}
// D = A(16x16 row) * B(16x8 col) + D, bf16 in, fp32 accum
__device__ __forceinline__ void mma_bf16(float* c, const uint32_t* a, const uint32_t* b) {
    asm volatile(
        "mma.sync.aligned.m16n8k16.row.col.f32.bf16.bf16.f32 "
        "{%0,%1,%2,%3}, {%4,%5,%6,%7}, {%8,%9}, {%0,%1,%2,%3};"
        : "+f"(c[0]), "+f"(c[1]), "+f"(c[2]), "+f"(c[3])
        : "r"(a[0]), "r"(a[1]), "r"(a[2]), "r"(a[3]), "r"(b[0]), "r"(b[1]));
}

__device__ __forceinline__ float sigmoidf_(float x) { return 1.f / (1.f + expf(-x)); }

// ---------------- convert: fp32 -> bf16 hi/lo ----------------
__global__ void convert_enc_kernel(const float* __restrict__ enc) {
    size_t i = ((size_t)blockIdx.x * 256 + threadIdx.x) * 4;
    float4 v = *(const float4*)(enc + i);
    __nv_bfloat16 h0 = __float2bfloat16(v.x), h1 = __float2bfloat16(v.y);
    __nv_bfloat16 h2 = __float2bfloat16(v.z), h3 = __float2bfloat16(v.w);
    __nv_bfloat16 l0 = __float2bfloat16(v.x - __bfloat162float(h0));
    __nv_bfloat16 l1 = __float2bfloat16(v.y - __bfloat162float(h1));
    __nv_bfloat16 l2 = __float2bfloat16(v.z - __bfloat162float(h2));
    __nv_bfloat16 l3 = __float2bfloat16(v.w - __bfloat162float(h3));
    __nv_bfloat162* ph = (__nv_bfloat162*)(g_Ahi + i);
    __nv_bfloat162* pl = (__nv_bfloat162*)(g_Alo + i);
    __nv_bfloat162 a; a.x = h0; a.y = h1; ph[0] = a;
    a.x = h2; a.y = h3; ph[1] = a;
    a.x = l0; a.y = l1; pl[0] = a;
    a.x = l2; a.y = l3; pl[1] = a;
}
__global__ void convert_w_kernel(const float* __restrict__ w0, const float* __restrict__ w1) {
    int which = blockIdx.y;
    const float* src = which ? w1 : w0;
    size_t i = ((size_t)blockIdx.x * 256 + threadIdx.x) * 4;
    float4 v = *(const float4*)(src + i);
    __nv_bfloat16 h0 = __float2bfloat16(v.x), h1 = __float2bfloat16(v.y);
    __nv_bfloat16 h2 = __float2bfloat16(v.z), h3 = __float2bfloat16(v.w);
    __nv_bfloat16 l0 = __float2bfloat16(v.x - __bfloat162float(h0));
    __nv_bfloat16 l1 = __float2bfloat16(v.y - __bfloat162float(h1));
    __nv_bfloat16 l2 = __float2bfloat16(v.z - __bfloat162float(h2));
    __nv_bfloat16 l3 = __float2bfloat16(v.w - __bfloat162float(h3));
    __nv_bfloat162* ph = (__nv_bfloat162*)(g_Whi[which] + i);
    __nv_bfloat162* pl = (__nv_bfloat162*)(g_Wlo[which] + i);
    __nv_bfloat162 a; a.x = h0; a.y = h1; ph[0] = a;
    a.x = h2; a.y = h3; ph[1] = a;
    a.x = l0; a.y = l1; pl[0] = a;
    a.x = l2; a.y = l3; pl[1] = a;
}

// ---------------- LSTM ----------------
__global__ void lstm_gates_kernel(const float* __restrict__ Wih,
                                  const float* __restrict__ Whh,
                                  const float* __restrict__ bih,
                                  const float* __restrict__ bhh,
                                  const float* x_in,
                                  const float* __restrict__ hprev) {
    int gw = (blockIdx.x * 256 + threadIdx.x) >> 5;
    int lane = threadIdx.x & 31;
    const float* x = x_in ? x_in : g_h;
    const float4* wi = (const float4*)(Wih + (size_t)gw * KDIM);
    const float4* wh = (const float4*)(Whh + (size_t)gw * KDIM);
    const float4* x4 = (const float4*)x;
    const float4* h4 = (const float4*)hprev;
    float s = 0.f;
#pragma unroll
    for (int i = 0; i < 8; ++i) {
        float4 a = wi[lane + i * 32], b = x4[lane + i * 32];
        s = fmaf(a.x, b.x, fmaf(a.y, b.y, fmaf(a.z, b.z, fmaf(a.w, b.w, s))));
        float4 c2 = wh[lane + i * 32], d2 = h4[lane + i * 32];
        s = fmaf(c2.x, d2.x, fmaf(c2.y, d2.y, fmaf(c2.z, d2.z, fmaf(c2.w, d2.w, s))));
    }
#pragma unroll
    for (int o = 16; o; o >>= 1) s += __shfl_xor_sync(0xffffffffu, s, o);
    if (lane == 0) g_gates[gw] = s + bih[gw] + bhh[gw];
}

__global__ void lstm_combine_kernel(const float* __restrict__ c_prev, int layer) {
    int j = threadIdx.x;
    float gi = g_gates[j];
    float gf = g_gates[1024 + j];
    float gg = g_gates[2048 + j];
    float go = g_gates[3072 + j];
    float c = sigmoidf_(gf) * c_prev[j] + sigmoidf_(gi) * tanhf(gg);
    float h = sigmoidf_(go) * tanhf(c);
    g_c[layer * 1024 + j] = c;
    g_h[layer * 1024 + j] = h;
}

// ---------------- generic 1024x1024 matvec ----------------
__global__ void matvec_kernel(const float* __restrict__ W,
                              const float* __restrict__ b0,
                              const float* __restrict__ b1,
                              const float* __restrict__ b2,
                              int x_sel, int out_sel) {
    int gw = (blockIdx.x * 256 + threadIdx.x) >> 5;
    int lane = threadIdx.x & 31;
    const float* x = (x_sel == 1) ? (g_h + 1024) : (x_sel == 2 ? g_wenc : g_context);
    const float4* wr = (const float4*)(W + (size_t)gw * KDIM);
    const float4* x4 = (const float4*)x;
    float s = 0.f;
#pragma unroll
    for (int i = 0; i < 8; ++i) {
        float4 a = wr[lane + i * 32], b = x4[lane + i * 32];
        s = fmaf(a.x, b.x, fmaf(a.y, b.y, fmaf(a.z, b.z, fmaf(a.w, b.w, s))));
    }
#pragma unroll
    for (int o = 16; o; o >>= 1) s += __shfl_xor_sync(0xffffffffu, s, o);
    if (lane == 0) {
        if (b0) s += b0[gw];
        if (b1) s += b1[gw];
        if (b2) s += b2[gw];
        if (out_sel == 0) g_zconst[gw] = s;
        else              g_context[gw] = s;
    }
}

// ---------------- tensor-core fused score GEMM (mma.sync, baseline PTX) ----------------
// logits[n] = sum_j v[j] * tanh( (A @ W^T)[n,j] + zconst[j] + cov[n]*wc[j] )
// A = enc (bf16 hi/lo), W = g_Whi/g_Wlo[which]. 3-product split: AhWh + AhWl + AlWh.
// CTA: 128 rows; 8 passes of 128 cols; K chunks of 32; double-buffered cp.async.
// SMEM tile rows padded to 80 B (32 bf16 data + 8 pad) -> 16B-aligned, ldmatrix
// bank-group = (5*row + kunit) mod 8: conflict-free.
#define ROWB     80
#define TILE_B   (128 * ROWB)          // 10240
#define ST_AHI   0
#define ST_ALO   TILE_B
#define ST_WHI   (2 * TILE_B)
#define ST_WLO   (3 * TILE_B)
#define STAGE_B  (4 * TILE_B)          // 40960
#define SCORE_DSMEM (2 * STAGE_B)      // 81920

__device__ __forceinline__ void load_chunk(uint32_t bu, int n0, int jt, int kc,
                                           int tid, int which) {
#pragma unroll
    for (int t = 0; t < 2; ++t) {
        int i = tid + t * 256;          // 0..511
        int row = i >> 2, ku = i & 3;
        uint32_t so = (uint32_t)(row * ROWB + ku * 16);
        size_t ga = (size_t)(n0 + row) * KDIM + kc * 32 + ku * 8;
        cpa16(bu + ST_AHI + so, g_Ahi + ga);
        cpa16(bu + ST_ALO + so, g_Alo + ga);
        size_t gw = (size_t)(jt * 128 + row) * KDIM + kc * 32 + ku * 8;
        cpa16(bu + ST_WHI + so, g_Whi[which] + gw);
        cpa16(bu + ST_WLO + so, g_Wlo[which] + gw);
    }
    cp_commit();
}

__global__ __launch_bounds__(256, 1)
void score_mma_kernel(int which,
                      const float* __restrict__ cov,
                      const float* __restrict__ wc,
                      const float* __restrict__ vvec) {
    extern __shared__ char dsm[];
    __shared__ float s_part[2][128];

    const int tid = threadIdx.x;
    const int lane = tid & 31;
    const int wid = tid >> 5;
    const int wr = wid & 3;       // row band: rows wr*32..+31
    const int wcb = wid >> 2;     // col band: cols wcb*64..+63
    const int n0 = blockIdx.x * 128;

    uint32_t sb = smem_u32(dsm);

    if (tid < 128) { s_part[0][tid] = 0.f; s_part[1][tid] = 0.f; }

    // cov values for the 4 rows this thread owns in the epilogue
    float mycov[4];
#pragma unroll
    for (int s = 0; s < 4; ++s)
        mycov[s] = cov[n0 + wr * 32 + (s >> 1) * 16 + (lane >> 2) + (s & 1) * 8];

    float acc[2][8][4];
#pragma unroll
    for (int ra = 0; ra < 2; ++ra)
#pragma unroll
        for (int na = 0; na < 8; ++na)
#pragma unroll
            for (int q = 0; q < 4; ++q) acc[ra][na][q] = 0.f;
    float rp[4] = {0.f, 0.f, 0.f, 0.f};

    // prologue
    load_chunk(sb, n0, 0, 0, tid, which);

    for (int it = 0; it < 256; ++it) {           // jt = it>>5, kc = it&31
        const int jt = it >> 5, kc = it & 31;
        if (it + 1 < 256) {
            load_chunk(sb + (uint32_t)((it + 1) & 1) * STAGE_B,
                       n0, (it + 1) >> 5, (it + 1) & 31, tid, which);
            cp_wait1();
        } else {
            cp_wait0();
        }
        __syncthreads();

        const uint32_t bu = sb + (uint32_t)(it & 1) * STAGE_B;
#pragma unroll
        for (int ks = 0; ks < 2; ++ks) {
            uint32_t a_hi[2][4], a_lo[2][4];
#pragma unroll
            for (int ra = 0; ra < 2; ++ra) {
                uint32_t addr = bu + ST_AHI
                    + (uint32_t)((wr * 32 + ra * 16 + (lane & 15)) * ROWB)
                    + (uint32_t)(((lane >> 4) * 8 + ks * 16) * 2);
                ldsm_x4(a_hi[ra], addr);
                ldsm_x4(a_lo[ra], addr + (ST_ALO - ST_AHI));
            }
            uint32_t b_hi[8][2], b_lo[8][2];
#pragma unroll
            for (int p = 0; p < 4; ++p) {
                int jr = wcb * 64 + p * 16 + ((lane >> 4) & 1) * 8 + (lane & 7);
                int ko = ((lane >> 3) & 1) * 8 + ks * 16;
                uint32_t addr = bu + ST_WHI + (uint32_t)(jr * ROWB) + (uint32_t)(ko * 2);
                uint32_t r4[4];
                ldsm_x4(r4, addr);
                b_hi[2 * p][0] = r4[0]; b_hi[2 * p][1] = r4[1];
                b_hi[2 * p + 1][0] = r4[2]; b_hi[2 * p + 1][1] = r4[3];
                ldsm_x4(r4, addr + (ST_WLO - ST_WHI));
                b_lo[2 * p][0] = r4[0]; b_lo[2 * p][1] = r4[1];
                b_lo[2 * p + 1][0] = r4[2]; b_lo[2 * p + 1][1] = r4[3];
            }
#pragma unroll
            for (int ra = 0; ra < 2; ++ra)
#pragma unroll
                for (int na = 0; na < 8; ++na) {
                    mma_bf16(acc[ra][na], a_hi[ra], b_hi[na]);
                    mma_bf16(acc[ra][na], a_hi[ra], b_lo[na]);
                    mma_bf16(acc[ra][na], a_lo[ra], b_hi[na]);
                }
        }

        if (kc == 31) {
            // epilogue for this 128-col pass: tanh + v-dot, all in registers
            const int jbase = jt * 128 + wcb * 64;
#pragma unroll
            for (int ra = 0; ra < 2; ++ra)
#pragma unroll
                for (int na = 0; na < 8; ++na)
#pragma unroll
                    for (int q = 0; q < 4; ++q) {
                        int j = jbase + na * 8 + (lane & 3) * 2 + (q & 1);
                        int s = ra * 2 + (q >> 1);
                        float a = acc[ra][na][q] + g_zconst[j] + mycov[s] * wc[j];
                        rp[s] += vvec[j] * tanhf(a);
                        acc[ra][na][q] = 0.f;
                    }
#pragma unroll
            for (int s = 0; s < 4; ++s) {
                rp[s] += __shfl_xor_sync(0xffffffffu, rp[s], 1);
                rp[s] += __shfl_xor_sync(0xffffffffu, rp[s], 2);
            }
            if ((lane & 3) == 0) {
#pragma unroll
                for (int s = 0; s < 4; ++s) {
                    int row = wr * 32 + (s >> 1) * 16 + (lane >> 2) + (s & 1) * 8;
                    s_part[wcb][row] += rp[s];
                }
            }
#pragma unroll
            for (int s = 0; s < 4; ++s) rp[s] = 0.f;
        }
        __syncthreads();   // compute done before next iter overwrites this buffer
    }

    if (tid < 128) g_logits[n0 + tid] = s_part[0][tid] + s_part[1][tid];
}

// ---------------- softmax (single CTA, deterministic) ----------------
__global__ void softmax_kernel(const float* __restrict__ vbp,
                               const float* __restrict__ cov,
                               float* __restrict__ prob_ext,
                               float* __restrict__ cov_out,
                               int do_relu) {
    __shared__ float shred[32];
    __shared__ float bval;
    int tid = threadIdx.x;
    float vb = vbp[0];
    float lmax = -3.4e38f;
    for (int n = tid; n < NROWS; n += 1024) {
        float l = g_logits[n] + vb;
        if (do_relu) l = fmaxf(l, 0.f);
        g_logits[n] = l;
        lmax = fmaxf(lmax, l);
    }
#pragma unroll
    for (int o = 16; o; o >>= 1) lmax = fmaxf(lmax, __shfl_xor_sync(0xffffffffu, lmax, o));
    if ((tid & 31) == 0) shred[tid >> 5] = lmax;
    __syncthreads();
    if (tid < 32) {
        float v = shred[tid];
#pragma unroll
        for (int o = 16; o; o >>= 1) v = fmaxf(v, __shfl_xor_sync(0xffffffffu, v, o));
        if (tid == 0) bval = v;
    }
    __syncthreads();
    float m = bval;
    float lsum = 0.f;
    for (int n = tid; n < NROWS; n += 1024) lsum += expf(g_logits[n] - m);
#pragma unroll
    for (int o = 16; o; o >>= 1) lsum += __shfl_xor_sync(0xffffffffu, lsum, o);
    __syncthreads();
    if ((tid & 31) == 0) shred[tid >> 5] = lsum;
    __syncthreads();
    if (tid < 32) {
        float v = shred[tid];
#pragma unroll
        for (int o = 16; o; o >>= 1) v += __shfl_xor_sync(0xffffffffu, v, o);
        if (tid == 0) bval = v;
    }
    __syncthreads();
    float inv = 1.f / bval;
    float* prob = prob_ext ? prob_ext : g_attn;
    for (int n = tid; n < NROWS; n += 1024) {
        float p = expf(g_logits[n] - m) * inv;
        prob[n] = p;
        if (cov_out) cov_out[n] = cov[n] + p;
    }
}

// ---------------- weighted column sum: g_wenc = enc^T @ attn ----------------
__global__ void wsum_partial_kernel(const float* __restrict__ enc) {
    int col = blockIdx.x * 256 + threadIdx.x;
    int n0 = blockIdx.y * 512;
    float s = 0.f;
#pragma unroll 4
    for (int n = n0; n < n0 + 512; ++n)
        s = fmaf(g_attn[n], enc[(size_t)n * KDIM + col], s);
    g_colpart[blockIdx.y * KDIM + col] = s;
}
__global__ void wsum_reduce_kernel() {
    int col = threadIdx.x;
    float s = 0.f;
#pragma unroll
    for (int i = 0; i < 64; ++i) s += g_colpart[i * KDIM + col];
    g_wenc[col] = s;
}

// ---------------- h/c output copy ----------------
__global__ void copy_hc_kernel(float* __restrict__ oh, float* __restrict__ oc) {
    int i = blockIdx.x * blockDim.x + threadIdx.x;
    if (i < 2048) {
        oh[i] = g_h[i];
        oc[i] = g_c[i];
    }
}

// ---------------- launch ----------------
extern "C" void kernel_launch(void* const* d_in, const int* in_sizes, int n_in,
                              void* d_out, int out_size) {
    (void)in_sizes; (void)n_in;
    const float* inp   = (const float*)d_in[0];
    const float* h0    = (const float*)d_in[1];
    const float* c0    = (const float*)d_in[2];
    const float* enc   = (const float*)d_in[3];
    const float* cov_g = (const float*)d_in[4];
    const float* cov_p = (const float*)d_in[5];
    const float* Wih   = (const float*)d_in[6];
    const float* Whh   = (const float*)d_in[7];
    const float* bih   = (const float*)d_in[8];
    const float* bhh   = (const float*)d_in[9];
    const float* gw1   = (const float*)d_in[10];
    const float* gb1   = (const float*)d_in[11];
    const float* gw2   = (const float*)d_in[12];
    const float* gb2   = (const float*)d_in[13];
    const float* gwc   = (const float*)d_in[14];
    const float* gbc   = (const float*)d_in[15];
    const float* gv    = (const float*)d_in[16];
    const float* gvb   = (const float*)d_in[17];
    const float* pw1   = (const float*)d_in[18];
    const float* pb1   = (const float*)d_in[19];
    const float* pw2   = (const float*)d_in[20];
    const float* pb2   = (const float*)d_in[21];
    const float* pwc   = (const float*)d_in[22];
    const float* pbc   = (const float*)d_in[23];
    const float* pv    = (const float*)d_in[24];
    const float* pvb   = (const float*)d_in[25];

    float* out = (float*)d_out;
    const int FULL = 32768 + 2048 + 2048 + 32768 + 32768;  // 102400
    bool full = out_size >= FULL;
    float* out_h  = full ? out + 32768 : nullptr;
    float* out_c  = full ? out + 34816 : nullptr;
    float* out_cg = full ? out + 36864 : nullptr;
    float* out_cp = full ? out + 69632 : nullptr;

    cudaFuncSetAttribute(score_mma_kernel,
                         cudaFuncAttributeMaxDynamicSharedMemorySize, SCORE_DSMEM);

    // bf16 hi/lo conversion
    convert_enc_kernel<<<32768, 256>>>(enc);
    convert_w_kernel<<<dim3(1024, 2), 256>>>(gw1, pw1);

    // LSTM layer 0 (x = _input, h/c = h0[0]/c0[0])
    lstm_gates_kernel<<<512, 256>>>(Wih, Whh, bih, bhh, inp, h0);
    lstm_combine_kernel<<<1, 1024>>>(c0, 0);
    // LSTM layer 1 (x = g_h[0:1024], h/c = h0[1]/c0[1])
    lstm_gates_kernel<<<512, 256>>>(Wih + (size_t)4096 * 1024, Whh + (size_t)4096 * 1024,
                                    bih + 4096, bhh + 4096, nullptr, h0 + 1024);
    lstm_combine_kernel<<<1, 1024>>>(c0 + 1024, 1);

    // zconst_g = g_w2 @ lstm_out + g_b2 + g_b1 + g_bc
    matvec_kernel<<<128, 256>>>(gw2, gb2, gb1, gbc, 1, 0);

    // glimpse attention logits (tensor cores, fused tanh/v-dot)
    score_mma_kernel<<<256, 256, SCORE_DSMEM>>>(0, cov_g, gwc, gv);
    softmax_kernel<<<1, 1024>>>(gvb, cov_g, nullptr, out_cg, 0);

    // weighted_enc = enc^T @ attn ; context = g_w1 @ weighted_enc + g_b1
    wsum_partial_kernel<<<dim3(4, 64), 256>>>(enc);
    wsum_reduce_kernel<<<1, 1024>>>();
    matvec_kernel<<<128, 256>>>(gw1, gb1, nullptr, nullptr, 2, 1);

    // zconst_p = p_w2 @ context + p_b2 + p_b1 + p_bc
    matvec_kernel<<<128, 256>>>(pw2, pb2, pb1, pbc, 3, 0);

    // pointer logits
    score_mma_kernel<<<256, 256, SCORE_DSMEM>>>(1, cov_p, pwc, pv);
    softmax_kernel<<<1, 1024>>>(pvb, cov_p, out, out_cp, 1);

    if (full) copy_hc_kernel<<<2, 1024>>>(out_h, out_c);
}

// round 12
// speedup vs baseline: 2.4899x; 1.0006x over previous
#include <cuda_runtime.h>
#include <cuda_bf16.h>
#include <math.h>
#include <cstdint>

#define NROWS 32768
#define KDIM  1024

// ---------------- device scratch (no allocations allowed) ----------------
__device__ alignas(16) float g_gates[4096];
__device__ alignas(16) float g_h[2048];
__device__ alignas(16) float g_c[2048];
__device__ alignas(16) float g_zconst[1024];
__device__ alignas(16) float g_context[1024];
__device__ alignas(16) float g_wenc[1024];
__device__ alignas(16) float g_logits[NROWS];
__device__ alignas(16) float g_attn[NROWS];
__device__ alignas(16) float g_colpart[64 * 1024];

// bf16 hi/lo split scratch for tensor-core GEMM
__device__ alignas(16) __nv_bfloat16 g_Ahi[(size_t)NROWS * KDIM];
__device__ alignas(16) __nv_bfloat16 g_Alo[(size_t)NROWS * KDIM];
__device__ alignas(16) __nv_bfloat16 g_Whi[2][(size_t)KDIM * KDIM];
__device__ alignas(16) __nv_bfloat16 g_Wlo[2][(size_t)KDIM * KDIM];

// ---------------- PTX helpers (baseline sm_80/sm_90 instructions ONLY) ----------------
__device__ __forceinline__ uint32_t smem_u32(const void* p) {
    uint32_t a;
    asm("{ .reg .u64 t; cvta.to.shared.u64 t, %1; cvt.u32.u64 %0, t; }" : "=r"(a) : "l"(p));
    return a;
}
__device__ __forceinline__ void cpa16(uint32_t s, const void* g) {
    asm volatile("cp.async.cg.shared.global [%0], [%1], 16;" :: "r"(s), "l"(g));
}
__device__ __forceinline__ void cp_commit() { asm volatile("cp.async.commit_group;" ::: "memory"); }
__device__ __forceinline__ void cp_wait1()  { asm volatile("cp.async.wait_group 1;" ::: "memory"); }
__device__ __forceinline__ void cp_wait0()  { asm volatile("cp.async.wait_group 0;" ::: "memory"); }

__device__ __forceinline__ void ldsm_x4(uint32_t* r, uint32_t addr) {
    asm volatile("ldmatrix.sync.aligned.m8n8.x4.shared.b16 {%0,%1,%2,%3}, [%4];"
                 : "=r"(r[0]), "=r"(r[1]), "=r"(r[2]), "=r"(r[3]) : "r"(addr));
}
// D = A(16x16 row) * B(16x8 col) + D, bf16 in, fp32 accum
__device__ __forceinline__ void mma_bf16(float* c, const uint32_t* a, const uint32_t* b) {
    asm volatile(
        "mma.sync.aligned.m16n8k16.row.col.f32.bf16.bf16.f32 "
        "{%0,%1,%2,%3}, {%4,%5,%6,%7}, {%8,%9}, {%0,%1,%2,%3};"
        : "+f"(c[0]), "+f"(c[1]), "+f"(c[2]), "+f"(c[3])
        : "r"(a[0]), "r"(a[1]), "r"(a[2]), "r"(a[3]), "r"(b[0]), "r"(b[1]));
}

__device__ __forceinline__ float sigmoidf_(float x) { return 1.f / (1.f + expf(-x)); }

// ---------------- convert: fp32 -> bf16 hi/lo ----------------
__global__ void convert_enc_kernel(const float* __restrict__ enc) {
    size_t i = ((size_t)blockIdx.x * 256 + threadIdx.x) * 4;
    float4 v = *(const float4*)(enc + i);
    __nv_bfloat16 h0 = __float2bfloat16(v.x), h1 = __float2bfloat16(v.y);
    __nv_bfloat16 h2 = __float2bfloat16(v.z), h3 = __float2bfloat16(v.w);
    __nv_bfloat16 l0 = __float2bfloat16(v.x - __bfloat162float(h0));
    __nv_bfloat16 l1 = __float2bfloat16(v.y - __bfloat162float(h1));
    __nv_bfloat16 l2 = __float2bfloat16(v.z - __bfloat162float(h2));
    __nv_bfloat16 l3 = __float2bfloat16(v.w - __bfloat162float(h3));
    __nv_bfloat162* ph = (__nv_bfloat162*)(g_Ahi + i);
    __nv_bfloat162* pl = (__nv_bfloat162*)(g_Alo + i);
    __nv_bfloat162 a; a.x = h0; a.y = h1; ph[0] = a;
    a.x = h2; a.y = h3; ph[1] = a;
    a.x = l0; a.y = l1; pl[0] = a;
    a.x = l2; a.y = l3; pl[1] = a;
}
__global__ void convert_w_kernel(const float* __restrict__ w0, const float* __restrict__ w1) {
    int which = blockIdx.y;
    const float* src = which ? w1 : w0;
    size_t i = ((size_t)blockIdx.x * 256 + threadIdx.x) * 4;
    float4 v = *(const float4*)(src + i);
    __nv_bfloat16 h0 = __float2bfloat16(v.x), h1 = __float2bfloat16(v.y);
    __nv_bfloat16 h2 = __float2bfloat16(v.z), h3 = __float2bfloat16(v.w);
    __nv_bfloat16 l0 = __float2bfloat16(v.x - __bfloat162float(h0));
    __nv_bfloat16 l1 = __float2bfloat16(v.y - __bfloat162float(h1));
    __nv_bfloat16 l2 = __float2bfloat16(v.z - __bfloat162float(h2));
    __nv_bfloat16 l3 = __float2bfloat16(v.w - __bfloat162float(h3));
    __nv_bfloat162* ph = (__nv_bfloat162*)(g_Whi[which] + i);
    __nv_bfloat162* pl = (__nv_bfloat162*)(g_Wlo[which] + i);
    __nv_bfloat162 a; a.x = h0; a.y = h1; ph[0] = a;
    a.x = h2; a.y = h3; ph[1] = a;
    a.x = l0; a.y = l1; pl[0] = a;
    a.x = l2; a.y = l3; pl[1] = a;
}

// ---------------- LSTM ----------------
__global__ void lstm_gates_kernel(const float* __restrict__ Wih,
                                  const float* __restrict__ Whh,
                                  const float* __restrict__ bih,
                                  const float* __restrict__ bhh,
                                  const float* x_in,
                                  const float* __restrict__ hprev) {
    int gw = (blockIdx.x * 256 + threadIdx.x) >> 5;
    int lane = threadIdx.x & 31;
    const float* x = x_in ? x_in : g_h;
    const float4* wi = (const float4*)(Wih + (size_t)gw * KDIM);
    const float4* wh = (const float4*)(Whh + (size_t)gw * KDIM);
    const float4* x4 = (const float4*)x;
    const float4* h4 = (const float4*)hprev;
    float s = 0.f;
#pragma unroll
    for (int i = 0; i < 8; ++i) {
        float4 a = wi[lane + i * 32], b = x4[lane + i * 32];
        s = fmaf(a.x, b.x, fmaf(a.y, b.y, fmaf(a.z, b.z, fmaf(a.w, b.w, s))));
        float4 c2 = wh[lane + i * 32], d2 = h4[lane + i * 32];
        s = fmaf(c2.x, d2.x, fmaf(c2.y, d2.y, fmaf(c2.z, d2.z, fmaf(c2.w, d2.w, s))));
    }
#pragma unroll
    for (int o = 16; o; o >>= 1) s += __shfl_xor_sync(0xffffffffu, s, o);
    if (lane == 0) g_gates[gw] = s + bih[gw] + bhh[gw];
}

__global__ void lstm_combine_kernel(const float* __restrict__ c_prev, int layer) {
    int j = threadIdx.x;
    float gi = g_gates[j];
    float gf = g_gates[1024 + j];
    float gg = g_gates[2048 + j];
    float go = g_gates[3072 + j];
    float c = sigmoidf_(gf) * c_prev[j] + sigmoidf_(gi) * tanhf(gg);
    float h = sigmoidf_(go) * tanhf(c);
    g_c[layer * 1024 + j] = c;
    g_h[layer * 1024 + j] = h;
}

// ---------------- generic 1024x1024 matvec ----------------
__global__ void matvec_kernel(const float* __restrict__ W,
                              const float* __restrict__ b0,
                              const float* __restrict__ b1,
                              const float* __restrict__ b2,
                              int x_sel, int out_sel) {
    int gw = (blockIdx.x * 256 + threadIdx.x) >> 5;
    int lane = threadIdx.x & 31;
    const float* x = (x_sel == 1) ? (g_h + 1024) : (x_sel == 2 ? g_wenc : g_context);
    const float4* wr = (const float4*)(W + (size_t)gw * KDIM);
    const float4* x4 = (const float4*)x;
    float s = 0.f;
#pragma unroll
    for (int i = 0; i < 8; ++i) {
        float4 a = wr[lane + i * 32], b = x4[lane + i * 32];
        s = fmaf(a.x, b.x, fmaf(a.y, b.y, fmaf(a.z, b.z, fmaf(a.w, b.w, s))));
    }
#pragma unroll
    for (int o = 16; o; o >>= 1) s += __shfl_xor_sync(0xffffffffu, s, o);
    if (lane == 0) {
        if (b0) s += b0[gw];
        if (b1) s += b1[gw];
        if (b2) s += b2[gw];
        if (out_sel == 0) g_zconst[gw] = s;
        else              g_context[gw] = s;
    }
}

// ---------------- tensor-core fused score GEMM (mma.sync, baseline PTX) ----------------
// logits[n] = sum_j v[j] * tanh( (A @ W^T)[n,j] + zconst[j] + cov[n]*wc[j] )
// A = enc (bf16 hi/lo), W = g_Whi/g_Wlo[which]. 3-product split: AhWh + AhWl + AlWh.
// CTA: 128 rows; 8 passes of 128 cols; K chunks of 32; double-buffered cp.async.
// SMEM tile rows padded to 80 B (32 bf16 data + 8 pad) -> 16B-aligned, ldmatrix
// bank-group = (5*row + kunit) mod 8: conflict-free.
#define ROWB     80
#define TILE_B   (128 * ROWB)          // 10240
#define ST_AHI   0
#define ST_ALO   TILE_B
#define ST_WHI   (2 * TILE_B)
#define ST_WLO   (3 * TILE_B)
#define STAGE_B  (4 * TILE_B)          // 40960
#define SCORE_DSMEM (2 * STAGE_B)      // 81920

__device__ __forceinline__ void load_chunk(uint32_t bu, int n0, int jt, int kc,
                                           int tid, int which) {
#pragma unroll
    for (int t = 0; t < 2; ++t) {
        int i = tid + t * 256;          // 0..511
        int row = i >> 2, ku = i & 3;
        uint32_t so = (uint32_t)(row * ROWB + ku * 16);
        size_t ga = (size_t)(n0 + row) * KDIM + kc * 32 + ku * 8;
        cpa16(bu + ST_AHI + so, g_Ahi + ga);
        cpa16(bu + ST_ALO + so, g_Alo + ga);
        size_t gw = (size_t)(jt * 128 + row) * KDIM + kc * 32 + ku * 8;
        cpa16(bu + ST_WHI + so, g_Whi[which] + gw);
        cpa16(bu + ST_WLO + so, g_Wlo[which] + gw);
    }
    cp_commit();
}

__global__ __launch_bounds__(256, 1)
void score_mma_kernel(int which,
                      const float* __restrict__ cov,
                      const float* __restrict__ wc,
                      const float* __restrict__ vvec) {
    extern __shared__ char dsm[];
    __shared__ float s_part[2][128];

    const int tid = threadIdx.x;
    const int lane = tid & 31;
    const int wid = tid >> 5;
    const int wr = wid & 3;       // row band: rows wr*32..+31
    const int wcb = wid >> 2;     // col band: cols wcb*64..+63
    const int n0 = blockIdx.x * 128;

    uint32_t sb = smem_u32(dsm);

    if (tid < 128) { s_part[0][tid] = 0.f; s_part[1][tid] = 0.f; }

    // cov values for the 4 rows this thread owns in the epilogue
    float mycov[4];
#pragma unroll
    for (int s = 0; s < 4; ++s)
        mycov[s] = cov[n0 + wr * 32 + (s >> 1) * 16 + (lane >> 2) + (s & 1) * 8];

    float acc[2][8][4];
#pragma unroll
    for (int ra = 0; ra < 2; ++ra)
#pragma unroll
        for (int na = 0; na < 8; ++na)
#pragma unroll
            for (int q = 0; q < 4; ++q) acc[ra][na][q] = 0.f;
    float rp[4] = {0.f, 0.f, 0.f, 0.f};

    // prologue
    load_chunk(sb, n0, 0, 0, tid, which);

    for (int it = 0; it < 256; ++it) {           // jt = it>>5, kc = it&31
        const int jt = it >> 5, kc = it & 31;
        if (it + 1 < 256) {
            load_chunk(sb + (uint32_t)((it + 1) & 1) * STAGE_B,
                       n0, (it + 1) >> 5, (it + 1) & 31, tid, which);
            cp_wait1();
        } else {
            cp_wait0();
        }
        __syncthreads();

        const uint32_t bu = sb + (uint32_t)(it & 1) * STAGE_B;
#pragma unroll
        for (int ks = 0; ks < 2; ++ks) {
            uint32_t a_hi[2][4], a_lo[2][4];
#pragma unroll
            for (int ra = 0; ra < 2; ++ra) {
                uint32_t addr = bu + ST_AHI
                    + (uint32_t)((wr * 32 + ra * 16 + (lane & 15)) * ROWB)
                    + (uint32_t)(((lane >> 4) * 8 + ks * 16) * 2);
                ldsm_x4(a_hi[ra], addr);
                ldsm_x4(a_lo[ra], addr + (ST_ALO - ST_AHI));
            }
            uint32_t b_hi[8][2], b_lo[8][2];
#pragma unroll
            for (int p = 0; p < 4; ++p) {
                int jr = wcb * 64 + p * 16 + ((lane >> 4) & 1) * 8 + (lane & 7);
                int ko = ((lane >> 3) & 1) * 8 + ks * 16;
                uint32_t addr = bu + ST_WHI + (uint32_t)(jr * ROWB) + (uint32_t)(ko * 2);
                uint32_t r4[4];
                ldsm_x4(r4, addr);
                b_hi[2 * p][0] = r4[0]; b_hi[2 * p][1] = r4[1];
                b_hi[2 * p + 1][0] = r4[2]; b_hi[2 * p + 1][1] = r4[3];
                ldsm_x4(r4, addr + (ST_WLO - ST_WHI));
                b_lo[2 * p][0] = r4[0]; b_lo[2 * p][1] = r4[1];
                b_lo[2 * p + 1][0] = r4[2]; b_lo[2 * p + 1][1] = r4[3];
            }
#pragma unroll
            for (int ra = 0; ra < 2; ++ra)
#pragma unroll
                for (int na = 0; na < 8; ++na) {
                    mma_bf16(acc[ra][na], a_hi[ra], b_hi[na]);
                    mma_bf16(acc[ra][na], a_hi[ra], b_lo[na]);
                    mma_bf16(acc[ra][na], a_lo[ra], b_hi[na]);
                }
        }

        if (kc == 31) {
            // epilogue for this 128-col pass: tanh + v-dot, all in registers
            const int jbase = jt * 128 + wcb * 64;
#pragma unroll
            for (int ra = 0; ra < 2; ++ra)
#pragma unroll
                for (int na = 0; na < 8; ++na)
#pragma unroll
                    for (int q = 0; q < 4; ++q) {
                        int j = jbase + na * 8 + (lane & 3) * 2 + (q & 1);
                        int s = ra * 2 + (q >> 1);
                        float a = acc[ra][na][q] + g_zconst[j] + mycov[s] * wc[j];
                        rp[s] += vvec[j] * tanhf(a);
                        acc[ra][na][q] = 0.f;
                    }
#pragma unroll
            for (int s = 0; s < 4; ++s) {
                rp[s] += __shfl_xor_sync(0xffffffffu, rp[s], 1);
                rp[s] += __shfl_xor_sync(0xffffffffu, rp[s], 2);
            }
            if ((lane & 3) == 0) {
#pragma unroll
                for (int s = 0; s < 4; ++s) {
                    int row = wr * 32 + (s >> 1) * 16 + (lane >> 2) + (s & 1) * 8;
                    s_part[wcb][row] += rp[s];
                }
            }
#pragma unroll
            for (int s = 0; s < 4; ++s) rp[s] = 0.f;
        }
        __syncthreads();   // compute done before next iter overwrites this buffer
    }

    if (tid < 128) g_logits[n0 + tid] = s_part[0][tid] + s_part[1][tid];
}

// ---------------- softmax (single CTA, deterministic) ----------------
__global__ void softmax_kernel(const float* __restrict__ vbp,
                               const float* __restrict__ cov,
                               float* __restrict__ prob_ext,
                               float* __restrict__ cov_out,
                               int do_relu) {
    __shared__ float shred[32];
    __shared__ float bval;
    int tid = threadIdx.x;
    float vb = vbp[0];
    float lmax = -3.4e38f;
    for (int n = tid; n < NROWS; n += 1024) {
        float l = g_logits[n] + vb;
        if (do_relu) l = fmaxf(l, 0.f);
        g_logits[n] = l;
        lmax = fmaxf(lmax, l);
    }
#pragma unroll
    for (int o = 16; o; o >>= 1) lmax = fmaxf(lmax, __shfl_xor_sync(0xffffffffu, lmax, o));
    if ((tid & 31) == 0) shred[tid >> 5] = lmax;
    __syncthreads();
    if (tid < 32) {
        float v = shred[tid];
#pragma unroll
        for (int o = 16; o; o >>= 1) v = fmaxf(v, __shfl_xor_sync(0xffffffffu, v, o));
        if (tid == 0) bval = v;
    }
    __syncthreads();
    float m = bval;
    float lsum = 0.f;
    for (int n = tid; n < NROWS; n += 1024) lsum += expf(g_logits[n] - m);
#pragma unroll
    for (int o = 16; o; o >>= 1) lsum += __shfl_xor_sync(0xffffffffu, lsum, o);
    __syncthreads();
    if ((tid & 31) == 0) shred[tid >> 5] = lsum;
    __syncthreads();
    if (tid < 32) {
        float v = shred[tid];
#pragma unroll
        for (int o = 16; o; o >>= 1) v += __shfl_xor_sync(0xffffffffu, v, o);
        if (tid == 0) bval = v;
    }
    __syncthreads();
    float inv = 1.f / bval;
    float* prob = prob_ext ? prob_ext : g_attn;
    for (int n = tid; n < NROWS; n += 1024) {
        float p = expf(g_logits[n] - m) * inv;
        prob[n] = p;
        if (cov_out) cov_out[n] = cov[n] + p;
    }
}

// ---------------- weighted column sum: g_wenc = enc^T @ attn ----------------
__global__ void wsum_partial_kernel(const float* __restrict__ enc) {
    int col = blockIdx.x * 256 + threadIdx.x;
    int n0 = blockIdx.y * 512;
    float s = 0.f;
#pragma unroll 4
    for (int n = n0; n < n0 + 512; ++n)
        s = fmaf(g_attn[n], enc[(size_t)n * KDIM + col], s);
    g_colpart[blockIdx.y * KDIM + col] = s;
}
__global__ void wsum_reduce_kernel() {
    int col = threadIdx.x;
    float s = 0.f;
#pragma unroll
    for (int i = 0; i < 64; ++i) s += g_colpart[i * KDIM + col];
    g_wenc[col] = s;
}

// ---------------- h/c output copy ----------------
__global__ void copy_hc_kernel(float* __restrict__ oh, float* __restrict__ oc) {
    int i = blockIdx.x * blockDim.x + threadIdx.x;
    if (i < 2048) {
        oh[i] = g_h[i];
        oc[i] = g_c[i];
    }
}

// ---------------- launch ----------------
extern "C" void kernel_launch(void* const* d_in, const int* in_sizes, int n_in,
                              void* d_out, int out_size) {
    (void)in_sizes; (void)n_in;
    const float* inp   = (const float*)d_in[0];
    const float* h0    = (const float*)d_in[1];
    const float* c0    = (const float*)d_in[2];
    const float* enc   = (const float*)d_in[3];
    const float* cov_g = (const float*)d_in[4];
    const float* cov_p = (const float*)d_in[5];
    const float* Wih   = (const float*)d_in[6];
    const float* Whh   = (const float*)d_in[7];
    const float* bih   = (const float*)d_in[8];
    const float* bhh   = (const float*)d_in[9];
    const float* gw1   = (const float*)d_in[10];
    const float* gb1   = (const float*)d_in[11];
    const float* gw2   = (const float*)d_in[12];
    const float* gb2   = (const float*)d_in[13];
    const float* gwc   = (const float*)d_in[14];
    const float* gbc   = (const float*)d_in[15];
    const float* gv    = (const float*)d_in[16];
    const float* gvb   = (const float*)d_in[17];
    const float* pw1   = (const float*)d_in[18];
    const float* pb1   = (const float*)d_in[19];
    const float* pw2   = (const float*)d_in[20];
    const float* pb2   = (const float*)d_in[21];
    const float* pwc   = (const float*)d_in[22];
    const float* pbc   = (const float*)d_in[23];
    const float* pv    = (const float*)d_in[24];
    const float* pvb   = (const float*)d_in[25];

    float* out = (float*)d_out;
    const int FULL = 32768 + 2048 + 2048 + 32768 + 32768;  // 102400
    bool full = out_size >= FULL;
    float* out_h  = full ? out + 32768 : nullptr;
    float* out_c  = full ? out + 34816 : nullptr;
    float* out_cg = full ? out + 36864 : nullptr;
    float* out_cp = full ? out + 69632 : nullptr;

    cudaFuncSetAttribute(score_mma_kernel,
                         cudaFuncAttributeMaxDynamicSharedMemorySize, SCORE_DSMEM);

    // bf16 hi/lo conversion
    convert_enc_kernel<<<32768, 256>>>(enc);
    convert_w_kernel<<<dim3(1024, 2), 256>>>(gw1, pw1);

    // LSTM layer 0 (x = _input, h/c = h0[0]/c0[0])
    lstm_gates_kernel<<<512, 256>>>(Wih, Whh, bih, bhh, inp, h0);
    lstm_combine_kernel<<<1, 1024>>>(c0, 0);
    // LSTM layer 1 (x = g_h[0:1024], h/c = h0[1]/c0[1])
    lstm_gates_kernel<<<512, 256>>>(Wih + (size_t)4096 * 1024, Whh + (size_t)4096 * 1024,
                                    bih + 4096, bhh + 4096, nullptr, h0 + 1024);
    lstm_combine_kernel<<<1, 1024>>>(c0 + 1024, 1);

    // zconst_g = g_w2 @ lstm_out + g_b2 + g_b1 + g_bc
    matvec_kernel<<<128, 256>>>(gw2, gb2, gb1, gbc, 1, 0);

    // glimpse attention logits (tensor cores, fused tanh/v-dot)
    score_mma_kernel<<<256, 256, SCORE_DSMEM>>>(0, cov_g, gwc, gv);
    softmax_kernel<<<1, 1024>>>(gvb, cov_g, nullptr, out_cg, 0);

    // weighted_enc = enc^T @ attn ; context = g_w1 @ weighted_enc + g_b1
    wsum_partial_kernel<<<dim3(4, 64), 256>>>(enc);
    wsum_reduce_kernel<<<1, 1024>>>();
    matvec_kernel<<<128, 256>>>(gw1, gb1, nullptr, nullptr, 2, 1);

    // zconst_p = p_w2 @ context + p_b2 + p_b1 + p_bc
    matvec_kernel<<<128, 256>>>(pw2, pb2, pb1, pbc, 3, 0);

    // pointer logits
    score_mma_kernel<<<256, 256, SCORE_DSMEM>>>(1, cov_p, pwc, pv);
    softmax_kernel<<<1, 1024>>>(pvb, cov_p, out, out_cp, 1);

    if (full) copy_hc_kernel<<<2, 1024>>>(out_h, out_c);
}